// round 15
// baseline (speedup 1.0000x reference)
#include <cuda_runtime.h>
#include <math.h>

#define T 4096
#define E 300
#define HID 512
#define G4 2048          // 4*HID
#define TAGS 12
#define NEGV -10000.0f
#define NB 32            // persistent blocks per direction in LSTM kernel

// ---------------- static device scratch (no allocations allowed) ----------------
__device__ float d_xg[2][T * G4];          // 2 x 32 MB: precomputed input projections
__device__ float d_Hs[2][T * HID];         // 2 x 8 MB : per-step hidden states
__device__ unsigned int d_cnt[2][T];       // per-(dir,step) arrival counters
__device__ float d_feats[T * TAGS];

// fma.rn.f32x2 (FFMA2): numerics cleared vs scalar FFMA (R3/R4 bit-identical)
#define FMA2(d, a, b, c) \
    asm("fma.rn.f32x2 %0, %1, %2, %3;" : "=l"(d) : "l"(a), "l"(b), "l"(c))

// MUFU.TANH path cleared in R10/R11 (passed, rel_err 5.7e-6)
__device__ __forceinline__ float tanh_fast(float x) {
    float r;
    asm("tanh.approx.f32 %0, %1;" : "=f"(r) : "f"(x));
    return r;
}
__device__ __forceinline__ float sigmoid_fast(float x) {
    return fmaf(tanh_fast(0.5f * x), 0.5f, 0.5f);
}

// ---------------- zero step counters (graph replays reuse state) ----------------
__global__ void init_kernel() {
    int i = blockIdx.x * 1024 + threadIdx.x;
    if (i < 2 * T) ((unsigned int*)d_cnt)[i] = 0u;
}

// ---------------- xg = emb[sentence] @ Wih^T + (bih + bhh), both dirs ----------------
// (UNCHANGED from R12/R13/R14)
__global__ void __launch_bounds__(256) xg_kernel(
    const int*   __restrict__ sent,
    const float* __restrict__ embt,
    const float* __restrict__ Wih_f,
    const float* __restrict__ bih_f,
    const float* __restrict__ bhh_f,
    const float* __restrict__ Wih_b,
    const float* __restrict__ bih_b,
    const float* __restrict__ bhh_b)
{
    const int dir = blockIdx.z;
    const float* Wih = dir ? Wih_b : Wih_f;
    const float* bih = dir ? bih_b : bih_f;
    const float* bhh = dir ? bhh_b : bhh_f;

    __shared__ __align__(16) float es[E * 32];   // es[k*32 + t]
    int t0 = blockIdx.x * 32;
    for (int i = threadIdx.x; i < 32 * E; i += 256) {
        int tt = i / E, k = i - tt * E;
        es[k * 32 + tt] = embt[(long long)sent[t0 + tt] * E + k];
    }
    __syncthreads();

    int r = blockIdx.y * 256 + threadIdx.x;
    const float4* w4 = (const float4*)(Wih + (long long)r * E);   // E=300 = 75 float4
    float bias = bih[r] + bhh[r];

    unsigned long long acc2[16];                  // 32 fp32 accumulators, packed
    {
        unsigned bb = __float_as_uint(bias);
        unsigned long long b2;
        asm("mov.b64 %0, {%1,%1};" : "=l"(b2) : "r"(bb));
#pragma unroll
        for (int i = 0; i < 16; i++) acc2[i] = b2;
    }

    for (int ko = 0; ko < 75; ko++) {
        float4 wq = __ldg(w4 + ko);
#pragma unroll
        for (int j = 0; j < 4; j++) {
            float wv = (j == 0) ? wq.x : (j == 1) ? wq.y : (j == 2) ? wq.z : wq.w;
            unsigned wb = __float_as_uint(wv);
            unsigned long long wvv;
            asm("mov.b64 %0, {%1,%1};" : "=l"(wvv) : "r"(wb));
            const ulonglong2* e2 = (const ulonglong2*)(es + (4 * ko + j) * 32);
#pragma unroll
            for (int q = 0; q < 8; q++) {
                ulonglong2 ev = e2[q];            // broadcast LDS.128
                FMA2(acc2[2 * q],     wvv, ev.x, acc2[2 * q]);
                FMA2(acc2[2 * q + 1], wvv, ev.y, acc2[2 * q + 1]);
            }
        }
    }

    float* xg = d_xg[dir];
#pragma unroll
    for (int i = 0; i < 16; i++) {
        float lo, hi;
        asm("mov.b64 {%0,%1}, %2;" : "=f"(lo), "=f"(hi) : "l"(acc2[i]));
        xg[(long long)(t0 + 2 * i)     * G4 + r] = lo;
        xg[(long long)(t0 + 2 * i + 1) * G4 + r] = hi;
    }
}

// ---------------- persistent BiLSTM recurrence ----------------
// Same structure as R14; ONE change: warp 1's reload is SPECULATIVE,
// overlapped with the counter poll. Loop invariant: when the loop exits,
// the h loads of the final iteration were issued after the acquire load
// (previous iteration) that observed cnt==NB -> ordered after all released
// producer stores. Deletes one serial L2 round trip per step.
__global__ void __launch_bounds__(256, 1) lstm_kernel(
    const float* __restrict__ Whh_f,
    const float* __restrict__ Whh_b)
{
    const int bx  = blockIdx.x;
    const int dir = bx >> 5;
    const int b   = bx & 31;
    const float* Whh = dir ? Whh_b : Whh_f;
    const float* xg  = d_xg[dir];
    float* Hst = d_Hs[dir];
    unsigned int* cnt = d_cnt[dir];

    const int tid = threadIdx.x;
    const int w = tid >> 5, l = tid & 31;
    const int p  = l >> 3;                  // 0..3 row pair within warp
    const int cI = l & 7;                   // 0..7 col chunk (64 cols)
    const int lr0 = 8 * w + 2 * p;          // local gate rows
    const int lr1 = lr0 + 1;
    const int grow0 = ((lr0 >> 4) << 9) + b * 16 + (lr0 & 15);
    const int grow1 = ((lr1 >> 4) << 9) + b * 16 + (lr1 & 15);

    // weights: 2 rows x 64 cols = 128 fp32 as 64 u64 pairs, in rotated order
    unsigned long long w0reg[32], w1reg[32];
#pragma unroll
    for (int i = 0; i < 16; i++) {
        int k = (i + cI) & 15;
        ulonglong2 v0 = *(const ulonglong2*)(Whh + (long long)grow0 * HID + cI * 64 + 4 * k);
        ulonglong2 v1 = *(const ulonglong2*)(Whh + (long long)grow1 * HID + cI * 64 + 4 * k);
        w0reg[2 * i] = v0.x; w0reg[2 * i + 1] = v0.y;
        w1reg[2 * i] = v1.x; w1reg[2 * i + 1] = v1.y;
    }

    __shared__ __align__(16) float h_sh[HID];
    __shared__ __align__(8) float part_full[64];   // complete gate-row sums

    float c = 0.f;                 // cell state (warp 0 lanes 0-15)
    float xgv[4] = {0.f, 0.f, 0.f, 0.f};

    h_sh[tid] = 0.f;
    h_sh[tid + 256] = 0.f;
    if (w == 0 && l < 16) {
        int t0 = dir ? (T - 1) : 0;
#pragma unroll
        for (int g = 0; g < 4; g++)
            xgv[g] = xg[(long long)t0 * G4 + (g << 9) + b * 16 + l];
    }
    __syncthreads();

    for (int s = 0; s < T; s++) {
        const int t = dir ? (T - 1 - s) : s;

        // ---- dot: 2 rows x 64-col chunk, rotated conflict-free LDS ----
        {
            unsigned long long a00 = 0ull, a01 = 0ull, a10 = 0ull, a11 = 0ull;
            const ulonglong2* h2 = (const ulonglong2*)h_sh;
#pragma unroll
            for (int i = 0; i < 16; i++) {
                int k = (i + cI) & 15;
                ulonglong2 hv = h2[(cI << 4) + k];   // 1-phase LDS.128
                FMA2(a00, w0reg[2 * i],     hv.x, a00);
                FMA2(a01, w0reg[2 * i + 1], hv.y, a01);
                FMA2(a10, w1reg[2 * i],     hv.x, a10);
                FMA2(a11, w1reg[2 * i + 1], hv.y, a11);
            }
            float x0, x1, x2, x3, y0, y1, y2, y3;
            asm("mov.b64 {%0,%1}, %2;" : "=f"(x0), "=f"(x1) : "l"(a00));
            asm("mov.b64 {%0,%1}, %2;" : "=f"(x2), "=f"(x3) : "l"(a01));
            asm("mov.b64 {%0,%1}, %2;" : "=f"(y0), "=f"(y1) : "l"(a10));
            asm("mov.b64 {%0,%1}, %2;" : "=f"(y2), "=f"(y3) : "l"(a11));
            float s0 = (x0 + x1) + (x2 + x3);
            float s1 = (y0 + y1) + (y2 + y3);
            // width-8 pairwise reduce over the 8 col chunks
            s0 += __shfl_down_sync(0xffffffffu, s0, 4, 8);
            s1 += __shfl_down_sync(0xffffffffu, s1, 4, 8);
            s0 += __shfl_down_sync(0xffffffffu, s0, 2, 8);
            s1 += __shfl_down_sync(0xffffffffu, s1, 2, 8);
            s0 += __shfl_down_sync(0xffffffffu, s0, 1, 8);
            s1 += __shfl_down_sync(0xffffffffu, s1, 1, 8);
            if (cI == 0)
                ((float2*)part_full)[(w << 2) + p] = make_float2(s0, s1);
        }
        __syncthreads();   // A: complete row sums in smem

        if (w == 0) {
            if (l < 16) {
                float g0 = part_full[l]      + xgv[0];
                float g1 = part_full[16 + l] + xgv[1];
                float g2 = part_full[32 + l] + xgv[2];
                float g3 = part_full[48 + l] + xgv[3];

                float ig = sigmoid_fast(g0);
                float fg = sigmoid_fast(g1);
                float og = sigmoid_fast(g3);
                float tg = tanh_fast(g2);
                c = fg * c + ig * tg;
                float hh = og * tanh_fast(c);

                asm volatile("st.global.cg.f32 [%0], %1;"
                             :: "l"(Hst + (long long)t * HID + b * 16 + l),
                                "f"(hh) : "memory");

                if (s + 1 < T) {
                    int tn = dir ? (t - 1) : (t + 1);
#pragma unroll
                    for (int g = 0; g < 4; g++)
                        xgv[g] = __ldcg(xg + (long long)tn * G4 + (g << 9) + b * 16 + l);
                }
            }
            __syncwarp();   // all lanes' h stores ordered before the release
            if (l == 0) {
                asm volatile("red.release.gpu.global.add.u32 [%0], %1;"
                             :: "l"(cnt + t), "r"(1u) : "memory");
            }
        } else if (w == 1 && s + 1 < T) {
            // ---- SPECULATIVE reload overlapped with counter poll ----
            // h loads of iteration k+1 are program-ordered after the acquire
            // load of iteration k; when that acquire saw cnt==NB, the final
            // iteration's h values are guaranteed current.
            const float4* hp4 = (const float4*)(Hst + (long long)t * HID);
            float4 r0, r1, r2, r3;
            unsigned cv = 0;
            bool ok;
            do {
                ok = (cv >= (unsigned)NB);
                r0 = __ldcg(hp4 + l);
                r1 = __ldcg(hp4 + 32 + l);
                r2 = __ldcg(hp4 + 64 + l);
                r3 = __ldcg(hp4 + 96 + l);
                asm volatile("ld.acquire.gpu.global.u32 %0, [%1];"
                             : "=r"(cv) : "l"(cnt + t) : "memory");
            } while (!ok);
            float4* hs4 = (float4*)h_sh;
            hs4[l]      = r0;
            hs4[32 + l] = r1;
            hs4[64 + l] = r2;
            hs4[96 + l] = r3;
        }
        __syncthreads();   // B: h(t) staged in smem for next step
    }
}

// ---------------- feats = [h_f, h_b] @ W_out^T + b_out ----------------
// grid 512, block 128, 8 timesteps per block. (UNCHANGED from R13)
__global__ void __launch_bounds__(128) feats_kernel(
    const float* __restrict__ W_out,
    const float* __restrict__ b_out)
{
    __shared__ __align__(16) float hb[2 * HID];
    int tid = threadIdx.x;
    int r = tid >> 3, cs = tid & 7;

    for (int tt = 0; tt < 8; tt++) {
        int t = blockIdx.x * 8 + tt;
        __syncthreads();
        ((float4*)hb)[tid]       = ((const float4*)(d_Hs[0] + (long long)t * HID))[tid];
        ((float4*)hb)[128 + tid] = ((const float4*)(d_Hs[1] + (long long)t * HID))[tid];
        __syncthreads();
        if (tid < 96) {
            const float4* wv = (const float4*)(W_out + r * 1024 + cs * 128);
            const float4* hv = (const float4*)(hb + cs * 128);
            float s0 = 0.f, s1 = 0.f, s2 = 0.f, s3 = 0.f;
#pragma unroll
            for (int i = 0; i < 32; i++) {
                float4 a = __ldg(wv + i);
                float4 bq = hv[i];
                s0 += a.x * bq.x; s1 += a.y * bq.y;
                s2 += a.z * bq.z; s3 += a.w * bq.w;
            }
            float sum = (s0 + s1) + (s2 + s3);
#pragma unroll
            for (int o = 4; o >= 1; o >>= 1)
                sum += __shfl_down_sync(0xffffffffu, sum, o);
            if (cs == 0)
                d_feats[t * TAGS + r] = sum + b_out[r];
        }
    }
}

// ---------------- Viterbi (UNCHANGED from R13: pairwise argmax tree) ----------------
#define AMAX2(mv, mi, xv, xi, yv, yi) \
    { bool _ge = (xv) >= (yv); mv = _ge ? (xv) : (yv); mi = _ge ? (xi) : (yi); }

__global__ void viterbi_kernel(const float* __restrict__ trans,
                               float* __restrict__ out)
{
    __shared__ unsigned long long bps[T];
    int l = threadIdx.x;

    float tr[TAGS];
    if (l < TAGS) {
#pragma unroll
        for (int pq = 0; pq < TAGS; pq++) tr[pq] = trans[l * TAGS + pq];
    } else {
#pragma unroll
        for (int pq = 0; pq < TAGS; pq++) tr[pq] = 0.f;
    }

    float fv = (l == 10) ? 0.f : NEGV;   // START = 10
    float featnext = (l < TAGS) ? d_feats[l] : 0.f;

    for (int t = 0; t < T; t++) {
        float feat = featnext;
        if (t + 1 < T && l < TAGS) featnext = d_feats[(t + 1) * TAGS + l];

        float v[TAGS];
#pragma unroll
        for (int pq = 0; pq < TAGS; pq++)
            v[pq] = __shfl_sync(0xffffffffu, fv, pq) + tr[pq];

        float a0v, a1v, a2v, a3v, a4v, a5v;  int a0i, a1i, a2i, a3i, a4i, a5i;
        AMAX2(a0v, a0i, v[0],  0,  v[1],  1);
        AMAX2(a1v, a1i, v[2],  2,  v[3],  3);
        AMAX2(a2v, a2i, v[4],  4,  v[5],  5);
        AMAX2(a3v, a3i, v[6],  6,  v[7],  7);
        AMAX2(a4v, a4i, v[8],  8,  v[9],  9);
        AMAX2(a5v, a5i, v[10], 10, v[11], 11);
        float b0v, b1v, b2v;  int b0i, b1i, b2i;
        AMAX2(b0v, b0i, a0v, a0i, a1v, a1i);
        AMAX2(b1v, b1i, a2v, a2i, a3v, a3i);
        AMAX2(b2v, b2i, a4v, a4i, a5v, a5i);
        float c0v;  int c0i;
        AMAX2(c0v, c0i, b0v, b0i, b1v, b1i);
        float m;  int am;
        AMAX2(m, am, c0v, c0i, b2v, b2i);

        unsigned lo = (l < 8)              ? ((unsigned)am << (4 * l))       : 0u;
        unsigned hi = (l >= 8 && l < TAGS) ? ((unsigned)am << (4 * (l - 8))) : 0u;
        lo = __reduce_add_sync(0xffffffffu, lo);
        hi = __reduce_add_sync(0xffffffffu, hi);
        if (l == 0) bps[t] = ((unsigned long long)hi << 32) | lo;

        fv = m + feat;
    }

    float term;
    if (l < TAGS) term = fv + trans[11 * TAGS + l];
    else          term = -3.4e38f;
    if (l == 11 || l == 10) term = NEGV;

    int best = 0; float sc = -3.4e38f;
#pragma unroll
    for (int pq = 0; pq < TAGS; pq++) {
        float v2 = __shfl_sync(0xffffffffu, term, pq);
        if (v2 > sc) { sc = v2; best = pq; }
    }

    __syncwarp();

    if (l == 0) {
        out[0] = sc;
        out[T] = (float)best;            // path[T-1]
        int tag = best;
        for (int t = T - 1; t >= 1; t--) {
            int prev = (int)((bps[t] >> (4 * tag)) & 15ull);
            out[t] = (float)prev;        // path[t-1] = chain[t]
            tag = prev;
        }
    }
}

// ---------------- launch ----------------
extern "C" void kernel_launch(void* const* d_in, const int* in_sizes, int n_in,
                              void* d_out, int out_size)
{
    const int*   sent  = (const int*)d_in[0];
    const float* embt  = (const float*)d_in[1];
    const float* Wih_f = (const float*)d_in[2];
    const float* Whh_f = (const float*)d_in[3];
    const float* bih_f = (const float*)d_in[4];
    const float* bhh_f = (const float*)d_in[5];
    const float* Wih_b = (const float*)d_in[6];
    const float* Whh_b = (const float*)d_in[7];
    const float* bih_b = (const float*)d_in[8];
    const float* bhh_b = (const float*)d_in[9];
    const float* W_out = (const float*)d_in[10];
    const float* b_out = (const float*)d_in[11];
    const float* trans = (const float*)d_in[12];
    float* out = (float*)d_out;

    init_kernel<<<8, 1024>>>();
    dim3 g(T / 32, G4 / 256, 2);
    xg_kernel<<<g, 256>>>(sent, embt, Wih_f, bih_f, bhh_f, Wih_b, bih_b, bhh_b);
    lstm_kernel<<<2 * NB, 256>>>(Whh_f, Whh_b);
    feats_kernel<<<512, 128>>>(W_out, b_out);
    viterbi_kernel<<<1, 32>>>(trans, out);
}